// round 16
// baseline (speedup 1.0000x reference)
#include <cuda_runtime.h>
#include <cuda_fp16.h>
#include <cstdint>
#include <cstddef>

#define H      2048
#define NH     16
#define HD     128
#define FF     8192
#define SEQ    2048
#define BATCH  2
#define MROWS  (BATCH*SEQ)   // 4096
#define EPS    1e-5f
#define SK_CTAS 304          // 2 CTAs/SM * 152 SMs, all co-resident

// ======================= scratch (device globals) ============================
__device__ float g_x2[MROWS * H];

__device__ __half g_qb [MROWS * H];
__device__ __half g_kb [MROWS * H];
__device__ __half g_vb [MROWS * H];

__device__ __half g_xn_h [MROWS * H];
__device__ __half g_xn2_h[MROWS * H];
__device__ __half g_h_h  [MROWS * FF];
__device__ __half g_wq_h [H * H];
__device__ __half g_wk_h [H * H];
__device__ __half g_wv_h [H * H];
__device__ __half g_up_h [FF * H];
__device__ __half g_dn_h [H * FF];

// stream-K scratch: one 128x128 fp32 slot per CTA + per-tile flags
__device__ float g_sk_part[SK_CTAS * 16384];
__device__ int   g_fl_q[1536];
__device__ int   g_fl_u[2048];
__device__ int   g_fl_d[512];

// ======================= helpers =============================================
__device__ __forceinline__ uint32_t smem_u32(const void* p) {
    uint32_t a;
    asm("{ .reg .u64 t; cvta.to.shared.u64 t, %1; cvt.u32.u64 %0, t; }"
        : "=r"(a) : "l"(p));
    return a;
}

__device__ __forceinline__ float ex2(float x) {
    float y;
    asm("ex2.approx.f32 %0, %1;" : "=f"(y) : "f"(x));
    return y;
}

#define CP_ASYNC16(smem, gmem) \
    asm volatile("cp.async.cg.shared.global [%0], [%1], 16;" :: "r"(smem), "l"(gmem))
#define CP_COMMIT() asm volatile("cp.async.commit_group;" ::: "memory")
#define CP_WAIT1()  asm volatile("cp.async.wait_group 1;" ::: "memory")
#define CP_WAIT0()  asm volatile("cp.async.wait_group 0;" ::: "memory")

#define LDSM4(r, addr) \
    asm volatile("ldmatrix.sync.aligned.m8n8.x4.shared.b16 {%0,%1,%2,%3}, [%4];" \
        : "=r"((r)[0]), "=r"((r)[1]), "=r"((r)[2]), "=r"((r)[3]) : "r"(addr))

#define LDSM4T(r, addr) \
    asm volatile("ldmatrix.sync.aligned.m8n8.x4.trans.shared.b16 {%0,%1,%2,%3}, [%4];" \
        : "=r"((r)[0]), "=r"((r)[1]), "=r"((r)[2]), "=r"((r)[3]) : "r"(addr))

#define MMA16816(d, a, b0, b1) \
    asm volatile("mma.sync.aligned.m16n8k16.row.col.f32.f16.f16.f32 " \
        "{%0,%1,%2,%3}, {%4,%5,%6,%7}, {%8,%9}, {%0,%1,%2,%3};" \
        : "+f"((d)[0]), "+f"((d)[1]), "+f"((d)[2]), "+f"((d)[3]) \
        : "r"((a)[0]), "r"((a)[1]), "r"((a)[2]), "r"((a)[3]), "r"(b0), "r"(b1))

// ======================= fused prep: weight convert + LN1 + flag zero ========
#define SQ4 (H * H / 4)
#define SU4 (FF * H / 4)
#define CONV_TOTAL  (3 * SQ4 + 2 * SU4)
#define CONV_BLOCKS (CONV_TOTAL / 2 / 256)

__device__ __forceinline__ void ln_row(
    const float* __restrict__ in, const float* __restrict__ gamma,
    const float* __restrict__ beta, __half* __restrict__ oh, int row)
{
    const float* p = in + (size_t)row * H;
    const int t = threadIdx.x;

    float4 v0 = ((const float4*)p)[t];
    float4 v1 = ((const float4*)p)[t + 256];

    float s  = v0.x + v0.y + v0.z + v0.w + v1.x + v1.y + v1.z + v1.w;
    float sq = v0.x*v0.x + v0.y*v0.y + v0.z*v0.z + v0.w*v0.w
             + v1.x*v1.x + v1.y*v1.y + v1.z*v1.z + v1.w*v1.w;

    #pragma unroll
    for (int o = 16; o > 0; o >>= 1) {
        s  += __shfl_down_sync(0xffffffffu, s,  o);
        sq += __shfl_down_sync(0xffffffffu, sq, o);
    }
    __shared__ float redS[8], redQ[8];
    const int w = t >> 5;
    if ((t & 31) == 0) { redS[w] = s; redQ[w] = sq; }
    __syncthreads();
    if (t < 32) {
        s  = (t < 8) ? redS[t] : 0.f;
        sq = (t < 8) ? redQ[t] : 0.f;
        #pragma unroll
        for (int o = 4; o > 0; o >>= 1) {
            s  += __shfl_down_sync(0xffffffffu, s,  o);
            sq += __shfl_down_sync(0xffffffffu, sq, o);
        }
        if (t == 0) { redS[0] = s; redQ[0] = sq; }
    }
    __syncthreads();
    const float mu  = redS[0] * (1.f / H);
    const float var = redQ[0] * (1.f / H) - mu * mu;
    const float rs  = rsqrtf(var + EPS);

    float4 g0 = ((const float4*)gamma)[t];
    float4 g1 = ((const float4*)gamma)[t + 256];
    float4 b0 = ((const float4*)beta )[t];
    float4 b1 = ((const float4*)beta )[t + 256];
    float4 o0, o1;
    o0.x = (v0.x - mu) * rs * g0.x + b0.x;
    o0.y = (v0.y - mu) * rs * g0.y + b0.y;
    o0.z = (v0.z - mu) * rs * g0.z + b0.z;
    o0.w = (v0.w - mu) * rs * g0.w + b0.w;
    o1.x = (v1.x - mu) * rs * g1.x + b1.x;
    o1.y = (v1.y - mu) * rs * g1.y + b1.y;
    o1.z = (v1.z - mu) * rs * g1.z + b1.z;
    o1.w = (v1.w - mu) * rs * g1.w + b1.w;

    __half2* ph = (__half2*)(oh + (size_t)row * H);
    ph[t * 2]       = __floats2half2_rn(o0.x, o0.y);
    ph[t * 2 + 1]   = __floats2half2_rn(o0.z, o0.w);
    ph[(t+256) * 2] = __floats2half2_rn(o1.x, o1.y);
    ph[(t+256)*2+1] = __floats2half2_rn(o1.z, o1.w);
}

__global__ void __launch_bounds__(256) prep_kernel(
    const float* __restrict__ wq, const float* __restrict__ wk,
    const float* __restrict__ wv, const float* __restrict__ up,
    const float* __restrict__ dn,
    __half* __restrict__ oq, __half* __restrict__ ok, __half* __restrict__ ov,
    __half* __restrict__ oup, __half* __restrict__ odn,
    const float* __restrict__ x, const float* __restrict__ ln1_s,
    const float* __restrict__ ln1_b, __half* __restrict__ xnh)
{
    if (blockIdx.x >= CONV_BLOCKS) {
        ln_row(x, ln1_s, ln1_b, xnh, blockIdx.x - CONV_BLOCKS);
        return;
    }
    if (blockIdx.x == 0) {     // zero stream-K flags (graph-replay safe)
        for (int i = threadIdx.x; i < 1536; i += 256) g_fl_q[i] = 0;
        for (int i = threadIdx.x; i < 2048; i += 256) g_fl_u[i] = 0;
        for (int i = threadIdx.x; i < 512;  i += 256) g_fl_d[i] = 0;
    }
    int i = (blockIdx.x * blockDim.x + threadIdx.x) * 2;
    const float* src;
    __half* dst;
    int j = i;
    if (j < 3 * SQ4) {
        const int s = j / SQ4;
        j -= s * SQ4;
        src = (s == 0) ? wq : (s == 1) ? wk : wv;
        dst = (s == 0) ? oq : (s == 1) ? ok : ov;
    } else {
        j -= 3 * SQ4;
        if (j < SU4) { src = up; dst = oup; }
        else         { src = dn; dst = odn; j -= SU4; }
    }
    float4 v0 = ((const float4*)src)[j];
    float4 v1 = ((const float4*)src)[j + 1];
    ((__half2*)dst)[j * 2]     = __floats2half2_rn(v0.x, v0.y);
    ((__half2*)dst)[j * 2 + 1] = __floats2half2_rn(v0.z, v0.w);
    ((__half2*)dst)[j * 2 + 2] = __floats2half2_rn(v1.x, v1.y);
    ((__half2*)dst)[j * 2 + 3] = __floats2half2_rn(v1.z, v1.w);
}

// ======================= LayerNorm -> fp16 (standalone for LN2) ==============
__global__ void __launch_bounds__(256) ln_h(
    const float* __restrict__ in, const float* __restrict__ gamma,
    const float* __restrict__ beta, __half* __restrict__ oh)
{
    ln_row(in, gamma, beta, oh, blockIdx.x);
}

// ======================= Stream-K HMMA GEMM ==================================
// 128x128 tiles, 4 warps (64x64 warp tile), 2 CTAs/SM, grid = SK_CTAS.
// Each CTA owns an equal contiguous range of k-units (tile k-len = K/64).
// Split tiles (<=2 contributors): head dumps fp32 partial + release flag;
// tail (owner) acquire-spins, adds, runs epilogue. Deterministic.
// MODE: 1 = +bias,+leaky -> fp16; 2 = +bias,+res -> f32; 4 = fused QKV fp16.
#define SKSMEM (3 * 32768)

template<int MODE>
__global__ void __launch_bounds__(128, 2) gemm_sk(
    const __half* __restrict__ A,
    const __half* __restrict__ B0, const __half* __restrict__ B1,
    const __half* __restrict__ B2,
    const float* __restrict__ bias, const float* __restrict__ res,
    float* __restrict__ C,
    __half* __restrict__ O0, __half* __restrict__ O1,
    __half* __restrict__ O2,
    int* __restrict__ flags,
    int tilesN, int K, int N)
{
    extern __shared__ __align__(1024) char smem[];
    __shared__ int s_src;
    const uint32_t sbase = smem_u32(smem);
    const int tid  = threadIdx.x;
    const int wid  = tid >> 5, lane = tid & 31;
    const int warp_m = (wid & 1) * 64;
    const int warp_n = (wid >> 1) * 64;
    const int cta = blockIdx.x;

    const int kU = K >> 6;
    const long total = (long)(MROWS / 128) * tilesN * kU;
    long beg  = total * cta / SK_CTAS;
    const long endr = total * (cta + 1) / SK_CTAS;

    const int ldr = tid >> 3;
    const int ldc = tid & 7;
    const int l7  = lane & 7;
    const int hi8 = ((lane >> 3) & 1) * 8;
    const int kh  = (lane >> 4) & 1;
    const int arow = warp_m + l7 + hi8;
    const int brow = warp_n + l7 + hi8;
    const int er = lane >> 2;
    const int ec = (lane & 3) * 2;

    while (beg < endr) {
        __syncthreads();   // smem buffers free from previous segment

        const int tile = (int)(beg / kU);
        const int ks   = (int)(beg - (long)tile * kU);
        const int ke   = (int)((endr - (long)tile * kU) < (long)kU
                                ? (endr - (long)tile * kU) : (long)kU);
        const int T    = ke - ks;

        const int mIdx = tile / tilesN;
        const int nIdx = tile % tilesN;
        const int m0 = mIdx * 128;
        int n0;
        const __half* Bsel;
        __half* Osel = nullptr;
        if (MODE == 4) {
            const int s = nIdx >> 4;           // 16 n-tiles per matrix
            n0 = (nIdx & 15) * 128;
            Bsel = (s == 0) ? B0 : (s == 1) ? B1 : B2;
            Osel = (s == 0) ? O0 : (s == 1) ? O1 : O2;
        } else {
            n0 = nIdx * 128;
            Bsel = B0;
            Osel = O0;
        }

        auto load_stage = [&](int t, int buf) {
            const int k0 = (ks + t) << 6;
            const uint32_t abase = sbase + buf * 32768;
            const uint32_t bbase = abase + 16384;
            #pragma unroll
            for (int it = 0; it < 8; ++it) {
                const int r = it * 16 + ldr;
                const uint32_t so = (uint32_t)(r * 128 + ((ldc ^ (r & 7)) * 16));
                CP_ASYNC16(abase + so, A + (size_t)(m0 + r) * K + k0 + ldc * 8);
            }
            #pragma unroll
            for (int it = 0; it < 8; ++it) {
                const int r = it * 16 + ldr;
                const uint32_t so = (uint32_t)(r * 128 + ((ldc ^ (r & 7)) * 16));
                CP_ASYNC16(bbase + so, Bsel + (size_t)(n0 + r) * K + k0 + ldc * 8);
            }
            CP_COMMIT();
        };

        float acc[4][8][4];
        #pragma unroll
        for (int a = 0; a < 4; ++a)
            #pragma unroll
            for (int b = 0; b < 8; ++b)
                #pragma unroll
                for (int c = 0; c < 4; ++c) acc[a][b][c] = 0.f;

        load_stage(0, 0);
        if (T > 1) load_stage(1, 1);

        uint32_t afr[2][4][4];
        uint32_t bfr[2][4][4];
        auto load_frags = [&](int fb, uint32_t ab, uint32_t bb, int kss) {
            const uint32_t swc = (uint32_t)(((2 * kss + kh) ^ l7) * 16);
            #pragma unroll
            for (int mt = 0; mt < 4; ++mt)
                LDSM4(afr[fb][mt], ab + (uint32_t)((arow + mt * 16) * 128) + swc);
            #pragma unroll
            for (int g = 0; g < 4; ++g)
                LDSM4(bfr[fb][g], bb + (uint32_t)((brow + g * 16) * 128) + swc);
        };

        if (T > 1) { CP_WAIT1(); } else { CP_WAIT0(); }
        __syncthreads();
        load_frags(0, sbase, sbase + 16384, 0);

        for (int t = 0; t < T; ++t) {
            const uint32_t abase = sbase + (t % 3) * 32768;
            const uint32_t bbase = abase + 16384;

            #pragma unroll
            for (int kss = 0; kss < 4; ++kss) {
                if (kss < 3)
                    load_frags((kss + 1) & 1, abase, bbase, kss + 1);
                const int cb = kss & 1;
                #pragma unroll
                for (int mt = 0; mt < 4; ++mt)
                    #pragma unroll
                    for (int nt = 0; nt < 8; ++nt)
                        MMA16816(acc[mt][nt], afr[cb][mt],
                                 bfr[cb][nt >> 1][nt & 1],
                                 bfr[cb][nt >> 1][(nt & 1) + 2]);
            }

            if (t + 1 < T) {
                CP_WAIT0();
                __syncthreads();
                const uint32_t nab = sbase + ((t + 1) % 3) * 32768;
                load_frags(0, nab, nab + 16384, 0);
                if (t + 2 < T) load_stage(t + 2, (t + 2) % 3);
            }
        }

        if (ks == 0 && ke < kU) {
            // head contributor: dump fp32 partial, release flag
            float* slot = g_sk_part + (size_t)cta * 16384 + tid * 128;
            #pragma unroll
            for (int mt = 0; mt < 4; ++mt)
                #pragma unroll
                for (int nt = 0; nt < 8; ++nt)
                    #pragma unroll
                    for (int i = 0; i < 4; ++i)
                        slot[(mt * 8 + nt) * 4 + i] = acc[mt][nt][i];
            __threadfence();
            __syncthreads();
            if (tid == 0) {
                int val = cta + 1;
                asm volatile("st.global.release.gpu.b32 [%0], %1;"
                             :: "l"(flags + tile), "r"(val) : "memory");
            }
        } else {
            if (ks > 0) {
                // tail owner of a split tile: wait for head partial, add
                if (tid == 0) {
                    int f;
                    do {
                        asm volatile("ld.global.acquire.gpu.b32 %0, [%1];"
                                     : "=r"(f) : "l"(flags + tile) : "memory");
                    } while (f == 0);
                    s_src = f - 1;
                }
                __syncthreads();
                const float* slot = g_sk_part + (size_t)s_src * 16384 + tid * 128;
                #pragma unroll
                for (int mt = 0; mt < 4; ++mt)
                    #pragma unroll
                    for (int nt = 0; nt < 8; ++nt)
                        #pragma unroll
                        for (int i = 0; i < 4; ++i)
                            acc[mt][nt][i] += slot[(mt * 8 + nt) * 4 + i];
            }
            // epilogue
            #pragma unroll
            for (int mt = 0; mt < 4; ++mt) {
                #pragma unroll
                for (int nt = 0; nt < 8; ++nt) {
                    const int row0 = m0 + warp_m + mt * 16 + er;
                    const int col  = n0 + warp_n + nt * 8 + ec;
                    float2 v0 = make_float2(acc[mt][nt][0], acc[mt][nt][1]);
                    float2 v1 = make_float2(acc[mt][nt][2], acc[mt][nt][3]);
                    if (MODE == 4) {
                        *(__half2*)&Osel[(size_t)row0 * N + col] =
                            __floats2half2_rn(v0.x, v0.y);
                        *(__half2*)&Osel[(size_t)(row0 + 8) * N + col] =
                            __floats2half2_rn(v1.x, v1.y);
                    } else if (MODE == 1) {
                        const float2 bv = *(const float2*)&bias[col];
                        v0.x += bv.x; v0.y += bv.y; v1.x += bv.x; v1.y += bv.y;
                        v0.x = (v0.x >= 0.f) ? v0.x : 0.01f * v0.x;
                        v0.y = (v0.y >= 0.f) ? v0.y : 0.01f * v0.y;
                        v1.x = (v1.x >= 0.f) ? v1.x : 0.01f * v1.x;
                        v1.y = (v1.y >= 0.f) ? v1.y : 0.01f * v1.y;
                        *(__half2*)&O0[(size_t)row0 * N + col] =
                            __floats2half2_rn(v0.x, v0.y);
                        *(__half2*)&O0[(size_t)(row0 + 8) * N + col] =
                            __floats2half2_rn(v1.x, v1.y);
                    } else {
                        const float2 bv = *(const float2*)&bias[col];
                        const float2 r0 = *(const float2*)&res[(size_t)row0 * N + col];
                        const float2 r1 = *(const float2*)&res[(size_t)(row0 + 8) * N + col];
                        v0.x += bv.x + r0.x; v0.y += bv.y + r0.y;
                        v1.x += bv.x + r1.x; v1.y += bv.y + r1.y;
                        *(float2*)&C[(size_t)row0 * N + col]       = v0;
                        *(float2*)&C[(size_t)(row0 + 8) * N + col] = v1;
                    }
                }
            }
        }

        beg = (long)tile * kU + ke;
    }
}

// ======================= HMMA flash attention (fp16) =========================
// Round-13 configuration (best measured): QB=64, 128 threads, 2-stage KV ring,
// 2 CTAs/SM, constant-shift softmax, register double-buffered frag pipelines.
#define QB 64
#define KB 64
#define SOFTMAX_SHIFT 8.0f
#define AOQ   0
#define AOKV  16384
#define AOPM  (16384 + 2 * 32768)            // 81920
#define ATT_SMEM (AOPM + 2 * 64 * 4 + 256)

__global__ void __launch_bounds__(128, 2) attn_hmma(
    const __half* __restrict__ q, const __half* __restrict__ k,
    const __half* __restrict__ v, const float* __restrict__ x,
    const unsigned char* __restrict__ pm, float* __restrict__ x2)
{
    extern __shared__ __align__(1024) char dsm[];
    const uint32_t sbase = smem_u32(dsm);
    float* pmf = (float*)(dsm + AOPM);

    const int b = blockIdx.z, h = blockIdx.y;
    const int qt = (SEQ / QB - 1) - blockIdx.x;     // heavy tiles first
    const int q0 = qt * QB;
    const int tid = threadIdx.x;
    const int wid = tid >> 5, lane = tid & 31;
    const int warp_q = wid * 16;
    const int qg0 = q0 + warp_q;
    const size_t bSeq = (size_t)b * SEQ;
    const size_t hoff = (size_t)h * HD;

    const int rowk = lane & 15;
    const int ch   = lane >> 4;
    const int er   = lane >> 2;
    const int ec2  = (lane & 3) * 2;

    const int T = qt + 1;
    const float C2 = 0.088388347648318447f * 1.4426950408889634f;

    auto load_kv = [&](int t, int buf) {
        const int k0 = t * KB;
        const uint32_t kb = sbase + AOKV + buf * 32768;
        const uint32_t vb = kb + 16384;
        const __half* kg = k + (bSeq + k0) * H + hoff;
        const __half* vg = v + (bSeq + k0) * H + hoff;
        #pragma unroll
        for (int it = 0; it < 8; ++it) {
            const int idx = tid + it * 128;
            const int r = idx >> 4, c = idx & 15;
            const uint32_t off = (uint32_t)(r * 256 + ((c ^ (r & 7)) << 4));
            CP_ASYNC16(kb + off, kg + (size_t)r * H + c * 8);
            CP_ASYNC16(vb + off, vg + (size_t)r * H + c * 8);
        }
        CP_COMMIT();
        if (tid < KB)
            pmf[buf * 64 + tid] = pm[bSeq + k0 + tid] ? -1e30f : -SOFTMAX_SHIFT;
    };

    {
        const __half* qg = q + (bSeq + q0) * H + hoff;
        #pragma unroll
        for (int it = 0; it < 8; ++it) {
            const int idx = tid + it * 128;
            const int r = idx >> 4, c = idx & 15;
            const uint32_t off = (uint32_t)(r * 256 + ((c ^ (r & 7)) << 4));
            CP_ASYNC16(sbase + AOQ + off, qg + (size_t)r * H + c * 8);
        }
    }
    load_kv(0, 0);
    if (T > 1) { load_kv(1, 1); CP_WAIT1(); } else { CP_WAIT0(); }
    __syncthreads();

    uint32_t qa[8][4];
    {
        const int rq = warp_q + rowk;
        const uint32_t rb = sbase + AOQ + rq * 256;
        const uint32_t swr = (uint32_t)(rq & 7);
        #pragma unroll
        for (int ds = 0; ds < 8; ++ds)
            LDSM4(qa[ds], rb + ((((uint32_t)(ds << 1) | ch) ^ swr) << 4));
    }

    float oacc[16][4];
    #pragma unroll
    for (int i = 0; i < 16; ++i)
        #pragma unroll
        for (int j = 0; j < 4; ++j) oacc[i][j] = 0.f;
    float l0r = 0.f, l1r = 0.f;
    const int qr0 = qg0 + er, qr1 = qg0 + er + 8;

    for (int t = 0; t < T; ++t) {
        const int buf = t & 1;
        const int k0 = t * KB;

        {
            const uint32_t kbs = sbase + AOKV + buf * 32768;
            const uint32_t vbs = kbs + 16384;

            float sacc[8][4];
            #pragma unroll
            for (int i = 0; i < 8; ++i)
                #pragma unroll
                for (int j = 0; j < 4; ++j) sacc[i][j] = 0.f;

            uint32_t kf[2][4];
            auto ldk = [&](int fb, int step) {
                const int kg = step >> 3, ds = step & 7;
                const int rk = kg * 16 + rowk;
                const uint32_t swr = (uint32_t)(rk & 7);
                LDSM4(kf[fb], kbs + rk * 256 +
                      ((((uint32_t)(ds << 1) | ch) ^ swr) << 4));
            };
            ldk(0, 0);
            #pragma unroll
            for (int step = 0; step < 32; ++step) {
                if (step < 31) ldk((step + 1) & 1, step + 1);
                const int kg = step >> 3, ds = step & 7;
                const int fb = step & 1;
                MMA16816(sacc[kg * 2],     qa[ds], kf[fb][0], kf[fb][2]);
                MMA16816(sacc[kg * 2 + 1], qa[ds], kf[fb][1], kf[fb][3]);
            }

            uint32_t vf[2][4];
            auto ldv = [&](int fb, int step) {
                const int kk = step >> 3, dg = step & 7;
                const int rk = kk * 16 + rowk;
                const uint32_t swr = (uint32_t)(rk & 7);
                LDSM4T(vf[fb], vbs + rk * 256 +
                       ((((uint32_t)(dg << 1) | ch) ^ swr) << 4));
            };
            ldv(0, 0);

            const float* spm = pmf + buf * 64;
            const bool fullvis = (k0 + KB - 1) <= qg0;
            uint32_t pa[4][4];
            float ps0 = 0.f, ps1 = 0.f;
            #pragma unroll
            for (int nt = 0; nt < 8; ++nt) {
                const int cb = nt * 8 + ec2;
                const float pv0 = spm[cb], pv1 = spm[cb + 1];
                const int c0g = k0 + cb;
                float s00 = fmaf(sacc[nt][0], C2, pv0);
                float s01 = fmaf(sacc[nt][1], C2, pv1);
                float s10 = fmaf(sacc[nt][2], C2, pv0);
                float s11 = fmaf(sacc[nt][3], C2, pv1);
                if (!fullvis) {
                    if (c0g > qr0)     s00 = -1e30f;
                    if (c0g + 1 > qr0) s01 = -1e30f;
                    if (c0g > qr1)     s10 = -1e30f;
                    if (c0g + 1 > qr1) s11 = -1e30f;
                }
                const float p00 = ex2(s00);
                const float p01 = ex2(s01);
                const float p10 = ex2(s10);
                const float p11 = ex2(s11);
                ps0 += p00 + p01; ps1 += p10 + p11;
                __half2 t0 = __floats2half2_rn(p00, p01);
                __half2 t1 = __floats2half2_rn(p10, p11);
                pa[nt >> 1][(nt & 1) << 1]       = *(uint32_t*)&t0;
                pa[nt >> 1][((nt & 1) << 1) + 1] = *(uint32_t*)&t1;
            }
            ps0 += __shfl_xor_sync(0xffffffffu, ps0, 1);
            ps0 += __shfl_xor_sync(0xffffffffu, ps0, 2);
            ps1 += __shfl_xor_sync(0xffffffffu, ps1, 1);
            ps1 += __shfl_xor_sync(0xffffffffu, ps1, 2);
            l0r += ps0;
            l1r += ps1;

            #pragma unroll
            for (int step = 0; step < 32; ++step) {
                if (step < 31) ldv((step + 1) & 1, step + 1);
                const int kk = step >> 3, dg = step & 7;
                const int fb = step & 1;
                MMA16816(oacc[dg * 2],     pa[kk], vf[fb][0], vf[fb][1]);
                MMA16816(oacc[dg * 2 + 1], pa[kk], vf[fb][2], vf[fb][3]);
            }
        }

        if (t + 1 < T) {
            __syncthreads();
            if (t + 2 < T) { load_kv(t + 2, buf); CP_WAIT1(); }
            else           { CP_WAIT0(); }
            __syncthreads();
        }
    }

    const float inv0 = 1.0f / l0r;
    const float inv1 = 1.0f / l1r;
    const size_t r0g = (bSeq + q0 + warp_q + er) * H + hoff + ec2;
    const size_t r1g = r0g + (size_t)8 * H;
    #pragma unroll
    for (int nt = 0; nt < 16; ++nt) {
        const int c = nt * 8;
        float2 w0, w1;
        w0.x = fmaf(oacc[nt][0], inv0, x[r0g + c]);
        w0.y = fmaf(oacc[nt][1], inv0, x[r0g + c + 1]);
        w1.x = fmaf(oacc[nt][2], inv1, x[r1g + c]);
        w1.y = fmaf(oacc[nt][3], inv1, x[r1g + c + 1]);
        *(float2*)&x2[r0g + c] = w0;
        *(float2*)&x2[r1g + c] = w1;
    }
}

// ======================= launch =============================================
extern "C" void kernel_launch(void* const* d_in, const int* in_sizes, int n_in,
                              void* d_out, int out_size)
{
    const float* x      = (const float*)d_in[0];
    const unsigned char* pm = (const unsigned char*)d_in[1];
    const float* W_Q    = (const float*)d_in[2];
    const float* W_K    = (const float*)d_in[3];
    const float* W_V    = (const float*)d_in[4];
    const float* up_w   = (const float*)d_in[5];
    const float* up_b   = (const float*)d_in[6];
    const float* down_w = (const float*)d_in[7];
    const float* down_b = (const float*)d_in[8];
    const float* ln1_s  = (const float*)d_in[9];
    const float* ln1_b  = (const float*)d_in[10];
    const float* ln2_s  = (const float*)d_in[11];
    const float* ln2_b  = (const float*)d_in[12];
    float* out = (float*)d_out;

    float *x2;
    __half *qb, *kb, *vb;
    __half *xnh, *xn2h, *hh;
    __half *wqh, *wkh, *wvh, *uph, *dnh;
    int *flq, *flu, *fld;
    cudaGetSymbolAddress((void**)&x2,   g_x2);
    cudaGetSymbolAddress((void**)&qb,   g_qb);
    cudaGetSymbolAddress((void**)&kb,   g_kb);
    cudaGetSymbolAddress((void**)&vb,   g_vb);
    cudaGetSymbolAddress((void**)&xnh,  g_xn_h);
    cudaGetSymbolAddress((void**)&xn2h, g_xn2_h);
    cudaGetSymbolAddress((void**)&hh,   g_h_h);
    cudaGetSymbolAddress((void**)&wqh,  g_wq_h);
    cudaGetSymbolAddress((void**)&wkh,  g_wk_h);
    cudaGetSymbolAddress((void**)&wvh,  g_wv_h);
    cudaGetSymbolAddress((void**)&uph,  g_up_h);
    cudaGetSymbolAddress((void**)&dnh,  g_dn_h);
    cudaGetSymbolAddress((void**)&flq,  g_fl_q);
    cudaGetSymbolAddress((void**)&flu,  g_fl_u);
    cudaGetSymbolAddress((void**)&fld,  g_fl_d);

    cudaFuncSetAttribute(attn_hmma,
                         cudaFuncAttributeMaxDynamicSharedMemorySize, ATT_SMEM);
    cudaFuncSetAttribute((const void*)gemm_sk<4>,
                         cudaFuncAttributeMaxDynamicSharedMemorySize, SKSMEM);
    cudaFuncSetAttribute((const void*)gemm_sk<1>,
                         cudaFuncAttributeMaxDynamicSharedMemorySize, SKSMEM);
    cudaFuncSetAttribute((const void*)gemm_sk<2>,
                         cudaFuncAttributeMaxDynamicSharedMemorySize, SKSMEM);

    // 1. fused prep: weight conversions + LN1 + flag zeroing (one launch)
    prep_kernel<<<CONV_BLOCKS + MROWS, 256>>>(
        W_Q, W_K, W_V, up_w, down_w, wqh, wkh, wvh, uph, dnh,
        x, ln1_s, ln1_b, xnh);
    // 2. fused QKV GEMM — stream-K over 1536 tiles (tilesN = 48)
    gemm_sk<4><<<SK_CTAS, 128, SKSMEM>>>(
        xnh, wqh, wkh, wvh, nullptr, nullptr, nullptr,
        qb, kb, vb, flq, 48, H, H);
    // 3. attention + residual (QB=64, 2 CTAs/SM, heavy tiles first)
    attn_hmma<<<dim3(SEQ / QB, NH, BATCH), 128, ATT_SMEM>>>(
        qb, kb, vb, x, pm, x2);
    // 4. LN2 -> fp16
    ln_h<<<MROWS, 256>>>(x2, ln2_s, ln2_b, xn2h);
    // 5. FFN up (+bias, leaky) — stream-K over 2048 tiles (tilesN = 64)
    gemm_sk<1><<<SK_CTAS, 128, SKSMEM>>>(
        xn2h, uph, nullptr, nullptr, up_b, nullptr, nullptr,
        hh, nullptr, nullptr, flu, 64, H, FF);
    // 6. FFN down (+bias, +residual) — stream-K over 512 tiles (tilesN = 16)
    gemm_sk<2><<<SK_CTAS, 128, SKSMEM>>>(
        hh, dnh, nullptr, nullptr, down_b, x2, out,
        nullptr, nullptr, nullptr, fld, 16, FF, H);
}

// round 17
// speedup vs baseline: 9.8664x; 9.8664x over previous
#include <cuda_runtime.h>
#include <cuda_fp16.h>
#include <cstdint>
#include <cstddef>

#define H      2048
#define NH     16
#define HD     128
#define FF     8192
#define SEQ    2048
#define BATCH  2
#define MROWS  (BATCH*SEQ)   // 4096
#define EPS    1e-5f

// ======================= scratch (device globals) ============================
__device__ float g_x2[MROWS * H];

__device__ __half g_qb [MROWS * H];
__device__ __half g_kb [MROWS * H];
__device__ __half g_vb [MROWS * H];

__device__ __half g_xn_h [MROWS * H];
__device__ __half g_xn2_h[MROWS * H];
__device__ __half g_h_h  [MROWS * FF];
__device__ __half g_wq_h [H * H];
__device__ __half g_wk_h [H * H];
__device__ __half g_wv_h [H * H];
__device__ __half g_up_h [FF * H];
__device__ __half g_dn_h [H * FF];

// ======================= helpers =============================================
__device__ __forceinline__ uint32_t smem_u32(const void* p) {
    uint32_t a;
    asm("{ .reg .u64 t; cvta.to.shared.u64 t, %1; cvt.u32.u64 %0, t; }"
        : "=r"(a) : "l"(p));
    return a;
}

__device__ __forceinline__ float ex2(float x) {
    float y;
    asm("ex2.approx.f32 %0, %1;" : "=f"(y) : "f"(x));
    return y;
}

#define CP_ASYNC16(smem, gmem) \
    asm volatile("cp.async.cg.shared.global [%0], [%1], 16;" :: "r"(smem), "l"(gmem))
#define CP_COMMIT() asm volatile("cp.async.commit_group;" ::: "memory")
#define CP_WAIT1()  asm volatile("cp.async.wait_group 1;" ::: "memory")
#define CP_WAIT0()  asm volatile("cp.async.wait_group 0;" ::: "memory")

#define LDSM4(r, addr) \
    asm volatile("ldmatrix.sync.aligned.m8n8.x4.shared.b16 {%0,%1,%2,%3}, [%4];" \
        : "=r"((r)[0]), "=r"((r)[1]), "=r"((r)[2]), "=r"((r)[3]) : "r"(addr))

#define LDSM4T(r, addr) \
    asm volatile("ldmatrix.sync.aligned.m8n8.x4.trans.shared.b16 {%0,%1,%2,%3}, [%4];" \
        : "=r"((r)[0]), "=r"((r)[1]), "=r"((r)[2]), "=r"((r)[3]) : "r"(addr))

#define MMA16816(d, a, b0, b1) \
    asm volatile("mma.sync.aligned.m16n8k16.row.col.f32.f16.f16.f32 " \
        "{%0,%1,%2,%3}, {%4,%5,%6,%7}, {%8,%9}, {%0,%1,%2,%3};" \
        : "+f"((d)[0]), "+f"((d)[1]), "+f"((d)[2]), "+f"((d)[3]) \
        : "r"((a)[0]), "r"((a)[1]), "r"((a)[2]), "r"((a)[3]), "r"(b0), "r"(b1))

// ======================= fused prep: weight convert + LN1 ====================
#define SQ4 (H * H / 4)
#define SU4 (FF * H / 4)
#define CONV_TOTAL  (3 * SQ4 + 2 * SU4)
#define CONV_BLOCKS (CONV_TOTAL / 2 / 256)

__device__ __forceinline__ void ln_row(
    const float* __restrict__ in, const float* __restrict__ gamma,
    const float* __restrict__ beta, __half* __restrict__ oh, int row)
{
    const float* p = in + (size_t)row * H;
    const int t = threadIdx.x;

    float4 v0 = ((const float4*)p)[t];
    float4 v1 = ((const float4*)p)[t + 256];

    float s  = v0.x + v0.y + v0.z + v0.w + v1.x + v1.y + v1.z + v1.w;
    float sq = v0.x*v0.x + v0.y*v0.y + v0.z*v0.z + v0.w*v0.w
             + v1.x*v1.x + v1.y*v1.y + v1.z*v1.z + v1.w*v1.w;

    #pragma unroll
    for (int o = 16; o > 0; o >>= 1) {
        s  += __shfl_down_sync(0xffffffffu, s,  o);
        sq += __shfl_down_sync(0xffffffffu, sq, o);
    }
    __shared__ float redS[8], redQ[8];
    const int w = t >> 5;
    if ((t & 31) == 0) { redS[w] = s; redQ[w] = sq; }
    __syncthreads();
    if (t < 32) {
        s  = (t < 8) ? redS[t] : 0.f;
        sq = (t < 8) ? redQ[t] : 0.f;
        #pragma unroll
        for (int o = 4; o > 0; o >>= 1) {
            s  += __shfl_down_sync(0xffffffffu, s,  o);
            sq += __shfl_down_sync(0xffffffffu, sq, o);
        }
        if (t == 0) { redS[0] = s; redQ[0] = sq; }
    }
    __syncthreads();
    const float mu  = redS[0] * (1.f / H);
    const float var = redQ[0] * (1.f / H) - mu * mu;
    const float rs  = rsqrtf(var + EPS);

    float4 g0 = ((const float4*)gamma)[t];
    float4 g1 = ((const float4*)gamma)[t + 256];
    float4 b0 = ((const float4*)beta )[t];
    float4 b1 = ((const float4*)beta )[t + 256];
    float4 o0, o1;
    o0.x = (v0.x - mu) * rs * g0.x + b0.x;
    o0.y = (v0.y - mu) * rs * g0.y + b0.y;
    o0.z = (v0.z - mu) * rs * g0.z + b0.z;
    o0.w = (v0.w - mu) * rs * g0.w + b0.w;
    o1.x = (v1.x - mu) * rs * g1.x + b1.x;
    o1.y = (v1.y - mu) * rs * g1.y + b1.y;
    o1.z = (v1.z - mu) * rs * g1.z + b1.z;
    o1.w = (v1.w - mu) * rs * g1.w + b1.w;

    __half2* ph = (__half2*)(oh + (size_t)row * H);
    ph[t * 2]       = __floats2half2_rn(o0.x, o0.y);
    ph[t * 2 + 1]   = __floats2half2_rn(o0.z, o0.w);
    ph[(t+256) * 2] = __floats2half2_rn(o1.x, o1.y);
    ph[(t+256)*2+1] = __floats2half2_rn(o1.z, o1.w);
}

// blocks [0, CONV_BLOCKS): weight conversion; [CONV_BLOCKS, +MROWS): LN1 rows
__global__ void __launch_bounds__(256) prep_kernel(
    const float* __restrict__ wq, const float* __restrict__ wk,
    const float* __restrict__ wv, const float* __restrict__ up,
    const float* __restrict__ dn,
    __half* __restrict__ oq, __half* __restrict__ ok, __half* __restrict__ ov,
    __half* __restrict__ oup, __half* __restrict__ odn,
    const float* __restrict__ x, const float* __restrict__ ln1_s,
    const float* __restrict__ ln1_b, __half* __restrict__ xnh)
{
    if (blockIdx.x >= CONV_BLOCKS) {
        ln_row(x, ln1_s, ln1_b, xnh, blockIdx.x - CONV_BLOCKS);
        return;
    }
    int i = (blockIdx.x * blockDim.x + threadIdx.x) * 2;
    const float* src;
    __half* dst;
    int j = i;
    if (j < 3 * SQ4) {
        const int s = j / SQ4;
        j -= s * SQ4;
        src = (s == 0) ? wq : (s == 1) ? wk : wv;
        dst = (s == 0) ? oq : (s == 1) ? ok : ov;
    } else {
        j -= 3 * SQ4;
        if (j < SU4) { src = up; dst = oup; }
        else         { src = dn; dst = odn; j -= SU4; }
    }
    float4 v0 = ((const float4*)src)[j];
    float4 v1 = ((const float4*)src)[j + 1];
    ((__half2*)dst)[j * 2]     = __floats2half2_rn(v0.x, v0.y);
    ((__half2*)dst)[j * 2 + 1] = __floats2half2_rn(v0.z, v0.w);
    ((__half2*)dst)[j * 2 + 2] = __floats2half2_rn(v1.x, v1.y);
    ((__half2*)dst)[j * 2 + 3] = __floats2half2_rn(v1.z, v1.w);
}

// ======================= LayerNorm -> fp16 (standalone for LN2) ==============
__global__ void __launch_bounds__(256) ln_h(
    const float* __restrict__ in, const float* __restrict__ gamma,
    const float* __restrict__ beta, __half* __restrict__ oh)
{
    ln_row(in, gamma, beta, oh, blockIdx.x);
}

// ======================= HMMA GEMM (128x128 CTA, 4 warps, 2 CTA/SM) ==========
#define GSMEM(BN_) (3 * (16384 + (BN_) * 128))

template<int MODE, int BN_, int NTH>
__global__ void __launch_bounds__(NTH, (NTH == 128 ? 2 : 1)) gemm_hmma(
    const __half* __restrict__ A,
    const __half* __restrict__ B0, const __half* __restrict__ B1,
    const __half* __restrict__ B2,
    const float* __restrict__ bias, const float* __restrict__ res,
    float* __restrict__ C,
    __half* __restrict__ O0, __half* __restrict__ O1,
    __half* __restrict__ O2,
    int M, int N, int K)
{
    constexpr int STAGE = 16384 + BN_ * 128;
    constexpr int RPI   = NTH / 8;
    extern __shared__ __align__(1024) char smem[];
    const uint32_t sbase = smem_u32(smem);
    const int tid  = threadIdx.x;
    const int wid  = tid >> 5, lane = tid & 31;
    const int m0 = blockIdx.y * 128;
    const int warp_m = (wid & 1) * 64;
    const int warp_n = (wid >> 1) * 64;

    int n0;
    const __half* Bsel;
    __half* Osel = nullptr;
    if (MODE == 4) {
        const int ng = blockIdx.x * BN_;
        const int s  = ng >> 11;
        n0 = ng & 2047;
        Bsel = (s == 0) ? B0 : (s == 1) ? B1 : B2;
        Osel = (s == 0) ? O0 : (s == 1) ? O1 : O2;
    } else {
        n0 = blockIdx.x * BN_;
        Bsel = B0;
        Osel = O0;
    }

    const int T = K >> 6;
    const int ldr = tid >> 3;
    const int ldc = tid & 7;

    auto load_stage = [&](int t, int buf) {
        const int k0 = t << 6;
        const uint32_t abase = sbase + buf * STAGE;
        const uint32_t bbase = abase + 16384;
        #pragma unroll
        for (int it = 0; it < 128 / RPI; ++it) {
            const int r = it * RPI + ldr;
            const uint32_t so = (uint32_t)(r * 128 + ((ldc ^ (r & 7)) * 16));
            CP_ASYNC16(abase + so, A + (size_t)(m0 + r) * K + k0 + ldc * 8);
        }
        #pragma unroll
        for (int it = 0; it < BN_ / RPI; ++it) {
            const int r = it * RPI + ldr;
            const uint32_t so = (uint32_t)(r * 128 + ((ldc ^ (r & 7)) * 16));
            CP_ASYNC16(bbase + so, Bsel + (size_t)(n0 + r) * K + k0 + ldc * 8);
        }
        CP_COMMIT();
    };

    float acc[4][8][4];
    #pragma unroll
    for (int a = 0; a < 4; ++a)
        #pragma unroll
        for (int b = 0; b < 8; ++b)
            #pragma unroll
            for (int c = 0; c < 4; ++c) acc[a][b][c] = 0.f;

    load_stage(0, 0);
    if (T > 1) load_stage(1, 1);

    const int l7  = lane & 7;
    const int hi8 = ((lane >> 3) & 1) * 8;
    const int kh  = (lane >> 4) & 1;
    const int arow = warp_m + l7 + hi8;
    const int brow = warp_n + l7 + hi8;

    uint32_t afr[2][4][4];
    uint32_t bfr[2][4][4];

    auto load_frags = [&](int fb, uint32_t ab, uint32_t bb, int ks) {
        const uint32_t swc = (uint32_t)(((2 * ks + kh) ^ l7) * 16);
        #pragma unroll
        for (int mt = 0; mt < 4; ++mt)
            LDSM4(afr[fb][mt], ab + (uint32_t)((arow + mt * 16) * 128) + swc);
        #pragma unroll
        for (int g = 0; g < 4; ++g)
            LDSM4(bfr[fb][g], bb + (uint32_t)((brow + g * 16) * 128) + swc);
    };

    if (T > 1) { CP_WAIT1(); } else { CP_WAIT0(); }
    __syncthreads();
    load_frags(0, sbase, sbase + 16384, 0);

    for (int t = 0; t < T; ++t) {
        const uint32_t abase = sbase + (t % 3) * STAGE;
        const uint32_t bbase = abase + 16384;

        #pragma unroll
        for (int ks = 0; ks < 4; ++ks) {
            if (ks < 3)
                load_frags((ks + 1) & 1, abase, bbase, ks + 1);
            const int cb = ks & 1;
            #pragma unroll
            for (int mt = 0; mt < 4; ++mt)
                #pragma unroll
                for (int nt = 0; nt < 8; ++nt)
                    MMA16816(acc[mt][nt], afr[cb][mt],
                             bfr[cb][nt >> 1][nt & 1],
                             bfr[cb][nt >> 1][(nt & 1) + 2]);
        }

        if (t + 1 < T) {
            CP_WAIT0();
            __syncthreads();
            const uint32_t nab = sbase + ((t + 1) % 3) * STAGE;
            load_frags(0, nab, nab + 16384, 0);
            if (t + 2 < T) load_stage(t + 2, (t + 2) % 3);
        }
    }

    // ---- epilogue ----
    const int er = lane >> 2;
    const int ec = (lane & 3) * 2;
    #pragma unroll
    for (int mt = 0; mt < 4; ++mt) {
        #pragma unroll
        for (int nt = 0; nt < 8; ++nt) {
            const int row0 = m0 + warp_m + mt * 16 + er;
            const int col  = n0 + warp_n + nt * 8 + ec;
            float2 v0 = make_float2(acc[mt][nt][0], acc[mt][nt][1]);
            float2 v1 = make_float2(acc[mt][nt][2], acc[mt][nt][3]);
            if (MODE == 4) {
                *(__half2*)&Osel[(size_t)row0 * N + col] =
                    __floats2half2_rn(v0.x, v0.y);
                *(__half2*)&Osel[(size_t)(row0 + 8) * N + col] =
                    __floats2half2_rn(v1.x, v1.y);
            } else if (MODE == 1) {
                const float2 bv = *(const float2*)&bias[col];
                v0.x += bv.x; v0.y += bv.y; v1.x += bv.x; v1.y += bv.y;
                v0.x = (v0.x >= 0.f) ? v0.x : 0.01f * v0.x;
                v0.y = (v0.y >= 0.f) ? v0.y : 0.01f * v0.y;
                v1.x = (v1.x >= 0.f) ? v1.x : 0.01f * v1.x;
                v1.y = (v1.y >= 0.f) ? v1.y : 0.01f * v1.y;
                *(__half2*)&O0[(size_t)row0 * N + col] =
                    __floats2half2_rn(v0.x, v0.y);
                *(__half2*)&O0[(size_t)(row0 + 8) * N + col] =
                    __floats2half2_rn(v1.x, v1.y);
            } else {
                const float2 bv = *(const float2*)&bias[col];
                const float2 r0 = *(const float2*)&res[(size_t)row0 * N + col];
                const float2 r1 = *(const float2*)&res[(size_t)(row0 + 8) * N + col];
                v0.x += bv.x + r0.x; v0.y += bv.y + r0.y;
                v1.x += bv.x + r1.x; v1.y += bv.y + r1.y;
                *(float2*)&C[(size_t)row0 * N + col]       = v0;
                *(float2*)&C[(size_t)(row0 + 8) * N + col] = v1;
            }
        }
    }
}

// ======================= HMMA flash attention (fp16) =========================
// Round-13 configuration (best measured): QB=64, 128 threads, 2-stage KV ring,
// 2 CTAs/SM, constant-shift softmax, register double-buffered frag pipelines.
#define QB 64
#define KB 64
#define SOFTMAX_SHIFT 8.0f
#define AOQ   0
#define AOKV  16384
#define AOPM  (16384 + 2 * 32768)            // 81920
#define ATT_SMEM (AOPM + 2 * 64 * 4 + 256)

__global__ void __launch_bounds__(128, 2) attn_hmma(
    const __half* __restrict__ q, const __half* __restrict__ k,
    const __half* __restrict__ v, const float* __restrict__ x,
    const unsigned char* __restrict__ pm, float* __restrict__ x2)
{
    extern __shared__ __align__(1024) char dsm[];
    const uint32_t sbase = smem_u32(dsm);
    float* pmf = (float*)(dsm + AOPM);

    const int b = blockIdx.z, h = blockIdx.y;
    const int qt = (SEQ / QB - 1) - blockIdx.x;     // heavy tiles first
    const int q0 = qt * QB;
    const int tid = threadIdx.x;
    const int wid = tid >> 5, lane = tid & 31;
    const int warp_q = wid * 16;
    const int qg0 = q0 + warp_q;
    const size_t bSeq = (size_t)b * SEQ;
    const size_t hoff = (size_t)h * HD;

    const int rowk = lane & 15;
    const int ch   = lane >> 4;
    const int er   = lane >> 2;
    const int ec2  = (lane & 3) * 2;

    const int T = qt + 1;
    const float C2 = 0.088388347648318447f * 1.4426950408889634f;

    auto load_kv = [&](int t, int buf) {
        const int k0 = t * KB;
        const uint32_t kb = sbase + AOKV + buf * 32768;
        const uint32_t vb = kb + 16384;
        const __half* kg = k + (bSeq + k0) * H + hoff;
        const __half* vg = v + (bSeq + k0) * H + hoff;
        #pragma unroll
        for (int it = 0; it < 8; ++it) {
            const int idx = tid + it * 128;
            const int r = idx >> 4, c = idx & 15;
            const uint32_t off = (uint32_t)(r * 256 + ((c ^ (r & 7)) << 4));
            CP_ASYNC16(kb + off, kg + (size_t)r * H + c * 8);
            CP_ASYNC16(vb + off, vg + (size_t)r * H + c * 8);
        }
        CP_COMMIT();
        if (tid < KB)
            pmf[buf * 64 + tid] = pm[bSeq + k0 + tid] ? -1e30f : -SOFTMAX_SHIFT;
    };

    {
        const __half* qg = q + (bSeq + q0) * H + hoff;
        #pragma unroll
        for (int it = 0; it < 8; ++it) {
            const int idx = tid + it * 128;
            const int r = idx >> 4, c = idx & 15;
            const uint32_t off = (uint32_t)(r * 256 + ((c ^ (r & 7)) << 4));
            CP_ASYNC16(sbase + AOQ + off, qg + (size_t)r * H + c * 8);
        }
    }
    load_kv(0, 0);
    if (T > 1) { load_kv(1, 1); CP_WAIT1(); } else { CP_WAIT0(); }
    __syncthreads();

    uint32_t qa[8][4];
    {
        const int rq = warp_q + rowk;
        const uint32_t rb = sbase + AOQ + rq * 256;
        const uint32_t swr = (uint32_t)(rq & 7);
        #pragma unroll
        for (int ds = 0; ds < 8; ++ds)
            LDSM4(qa[ds], rb + ((((uint32_t)(ds << 1) | ch) ^ swr) << 4));
    }

    float oacc[16][4];
    #pragma unroll
    for (int i = 0; i < 16; ++i)
        #pragma unroll
        for (int j = 0; j < 4; ++j) oacc[i][j] = 0.f;
    float l0r = 0.f, l1r = 0.f;
    const int qr0 = qg0 + er, qr1 = qg0 + er + 8;

    for (int t = 0; t < T; ++t) {
        const int buf = t & 1;
        const int k0 = t * KB;

        {
            const uint32_t kbs = sbase + AOKV + buf * 32768;
            const uint32_t vbs = kbs + 16384;

            // ---- S = Q K^T : 32-step pipelined loop ----
            float sacc[8][4];
            #pragma unroll
            for (int i = 0; i < 8; ++i)
                #pragma unroll
                for (int j = 0; j < 4; ++j) sacc[i][j] = 0.f;

            uint32_t kf[2][4];
            auto ldk = [&](int fb, int step) {
                const int kg = step >> 3, ds = step & 7;
                const int rk = kg * 16 + rowk;
                const uint32_t swr = (uint32_t)(rk & 7);
                LDSM4(kf[fb], kbs + rk * 256 +
                      ((((uint32_t)(ds << 1) | ch) ^ swr) << 4));
            };
            ldk(0, 0);
            #pragma unroll
            for (int step = 0; step < 32; ++step) {
                if (step < 31) ldk((step + 1) & 1, step + 1);
                const int kg = step >> 3, ds = step & 7;
                const int fb = step & 1;
                MMA16816(sacc[kg * 2],     qa[ds], kf[fb][0], kf[fb][2]);
                MMA16816(sacc[kg * 2 + 1], qa[ds], kf[fb][1], kf[fb][3]);
            }

            // first V fragment prefetch under softmax ALU work
            uint32_t vf[2][4];
            auto ldv = [&](int fb, int step) {
                const int kk = step >> 3, dg = step & 7;
                const int rk = kk * 16 + rowk;
                const uint32_t swr = (uint32_t)(rk & 7);
                LDSM4T(vf[fb], vbs + rk * 256 +
                       ((((uint32_t)(dg << 1) | ch) ^ swr) << 4));
            };
            ldv(0, 0);

            // ---- constant-shift softmax ----
            const float* spm = pmf + buf * 64;
            const bool fullvis = (k0 + KB - 1) <= qg0;
            uint32_t pa[4][4];
            float ps0 = 0.f, ps1 = 0.f;
            #pragma unroll
            for (int nt = 0; nt < 8; ++nt) {
                const int cb = nt * 8 + ec2;
                const float pv0 = spm[cb], pv1 = spm[cb + 1];
                const int c0g = k0 + cb;
                float s00 = fmaf(sacc[nt][0], C2, pv0);
                float s01 = fmaf(sacc[nt][1], C2, pv1);
                float s10 = fmaf(sacc[nt][2], C2, pv0);
                float s11 = fmaf(sacc[nt][3], C2, pv1);
                if (!fullvis) {
                    if (c0g > qr0)     s00 = -1e30f;
                    if (c0g + 1 > qr0) s01 = -1e30f;
                    if (c0g > qr1)     s10 = -1e30f;
                    if (c0g + 1 > qr1) s11 = -1e30f;
                }
                const float p00 = ex2(s00);
                const float p01 = ex2(s01);
                const float p10 = ex2(s10);
                const float p11 = ex2(s11);
                ps0 += p00 + p01; ps1 += p10 + p11;
                __half2 t0 = __floats2half2_rn(p00, p01);
                __half2 t1 = __floats2half2_rn(p10, p11);
                pa[nt >> 1][(nt & 1) << 1]       = *(uint32_t*)&t0;
                pa[nt >> 1][((nt & 1) << 1) + 1] = *(uint32_t*)&t1;
            }
            ps0 += __shfl_xor_sync(0xffffffffu, ps0, 1);
            ps0 += __shfl_xor_sync(0xffffffffu, ps0, 2);
            ps1 += __shfl_xor_sync(0xffffffffu, ps1, 1);
            ps1 += __shfl_xor_sync(0xffffffffu, ps1, 2);
            l0r += ps0;
            l1r += ps1;

            // ---- O += P V : 32-step pipelined loop ----
            #pragma unroll
            for (int step = 0; step < 32; ++step) {
                if (step < 31) ldv((step + 1) & 1, step + 1);
                const int kk = step >> 3, dg = step & 7;
                const int fb = step & 1;
                MMA16816(oacc[dg * 2],     pa[kk], vf[fb][0], vf[fb][1]);
                MMA16816(oacc[dg * 2 + 1], pa[kk], vf[fb][2], vf[fb][3]);
            }
        }

        if (t + 1 < T) {
            __syncthreads();
            if (t + 2 < T) { load_kv(t + 2, buf); CP_WAIT1(); }
            else           { CP_WAIT0(); }
            __syncthreads();
        }
    }

    const float inv0 = 1.0f / l0r;
    const float inv1 = 1.0f / l1r;
    const size_t r0g = (bSeq + q0 + warp_q + er) * H + hoff + ec2;
    const size_t r1g = r0g + (size_t)8 * H;
    #pragma unroll
    for (int nt = 0; nt < 16; ++nt) {
        const int c = nt * 8;
        float2 w0, w1;
        w0.x = fmaf(oacc[nt][0], inv0, x[r0g + c]);
        w0.y = fmaf(oacc[nt][1], inv0, x[r0g + c + 1]);
        w1.x = fmaf(oacc[nt][2], inv1, x[r1g + c]);
        w1.y = fmaf(oacc[nt][3], inv1, x[r1g + c + 1]);
        *(float2*)&x2[r0g + c] = w0;
        *(float2*)&x2[r1g + c] = w1;
    }
}

// ======================= launch =============================================
extern "C" void kernel_launch(void* const* d_in, const int* in_sizes, int n_in,
                              void* d_out, int out_size)
{
    const float* x      = (const float*)d_in[0];
    const unsigned char* pm = (const unsigned char*)d_in[1];
    const float* W_Q    = (const float*)d_in[2];
    const float* W_K    = (const float*)d_in[3];
    const float* W_V    = (const float*)d_in[4];
    const float* up_w   = (const float*)d_in[5];
    const float* up_b   = (const float*)d_in[6];
    const float* down_w = (const float*)d_in[7];
    const float* down_b = (const float*)d_in[8];
    const float* ln1_s  = (const float*)d_in[9];
    const float* ln1_b  = (const float*)d_in[10];
    const float* ln2_s  = (const float*)d_in[11];
    const float* ln2_b  = (const float*)d_in[12];
    float* out = (float*)d_out;

    float *x2;
    __half *qb, *kb, *vb;
    __half *xnh, *xn2h, *hh;
    __half *wqh, *wkh, *wvh, *uph, *dnh;
    cudaGetSymbolAddress((void**)&x2,   g_x2);
    cudaGetSymbolAddress((void**)&qb,   g_qb);
    cudaGetSymbolAddress((void**)&kb,   g_kb);
    cudaGetSymbolAddress((void**)&vb,   g_vb);
    cudaGetSymbolAddress((void**)&xnh,  g_xn_h);
    cudaGetSymbolAddress((void**)&xn2h, g_xn2_h);
    cudaGetSymbolAddress((void**)&hh,   g_h_h);
    cudaGetSymbolAddress((void**)&wqh,  g_wq_h);
    cudaGetSymbolAddress((void**)&wkh,  g_wk_h);
    cudaGetSymbolAddress((void**)&wvh,  g_wv_h);
    cudaGetSymbolAddress((void**)&uph,  g_up_h);
    cudaGetSymbolAddress((void**)&dnh,  g_dn_h);

    cudaFuncSetAttribute(attn_hmma,
                         cudaFuncAttributeMaxDynamicSharedMemorySize, ATT_SMEM);
    cudaFuncSetAttribute((const void*)gemm_hmma<4, 128, 128>,
                         cudaFuncAttributeMaxDynamicSharedMemorySize, GSMEM(128));
    cudaFuncSetAttribute((const void*)gemm_hmma<1, 128, 128>,
                         cudaFuncAttributeMaxDynamicSharedMemorySize, GSMEM(128));
    cudaFuncSetAttribute((const void*)gemm_hmma<2, 128, 128>,
                         cudaFuncAttributeMaxDynamicSharedMemorySize, GSMEM(128));

    // 1. fused prep: weight conversions + LN1 (one launch)
    prep_kernel<<<CONV_BLOCKS + MROWS, 256>>>(
        W_Q, W_K, W_V, up_w, down_w, wqh, wkh, wvh, uph, dnh,
        x, ln1_s, ln1_b, xnh);
    // 2. fused QKV GEMM (fp16 out) — 1536 CTAs, 2/SM
    gemm_hmma<4, 128, 128><<<dim3(3 * H / 128, MROWS / 128), 128, GSMEM(128)>>>(
        xnh, wqh, wkh, wvh, nullptr, nullptr, nullptr,
        qb, kb, vb, MROWS, H, H);
    // 3. attention + residual (QB=64, 2 CTAs/SM, heavy tiles first)
    attn_hmma<<<dim3(SEQ / QB, NH, BATCH), 128, ATT_SMEM>>>(
        qb, kb, vb, x, pm, x2);
    // 4. LN2 -> fp16
    ln_h<<<MROWS, 256>>>(x2, ln2_s, ln2_b, xn2h);
    // 5. FFN up (+bias, leaky) -> fp16 — 2048 CTAs, 2/SM
    gemm_hmma<1, 128, 128><<<dim3(FF / 128, MROWS / 128), 128, GSMEM(128)>>>(
        xn2h, uph, nullptr, nullptr, up_b, nullptr, nullptr,
        hh, nullptr, nullptr, MROWS, FF, H);
    // 6. FFN down (+bias, +residual) -> output — 512 CTAs, 2/SM
    gemm_hmma<2, 128, 128><<<dim3(H / 128, MROWS / 128), 128, GSMEM(128)>>>(
        hh, dnh, nullptr, nullptr, down_b, x2, out,
        nullptr, nullptr, nullptr, MROWS, H, FF);
}